// round 16
// baseline (speedup 1.0000x reference)
#include <cuda_runtime.h>
#include <cuda_fp16.h>
#include <cstdint>

// GAE reverse scan, 3-pass chunked linear recurrence with compressed
// intermediate. R16: columns split into two independent halves run as a
// SKEWED two-stream pipeline so read-heavy pass1(h1) overlaps write-heavy
// pass2(h0), mixing the DRAM read/write streams.
//
//   adv_t = delta_t + c_t * adv_{t+1},  c_t = GL*(1-done_{t+1})
//   delta_t = r_t + GAMMA*v_{t+1}*(1-done_{t+1}) - v_t   (v_T=0, done_T=1)
// Output: d_out[0:T*N] = advantages, d_out[T*N:2*T*N] = advantages + values.

#define T_DIM   2048
#define N_DIM   4096
#define NH      (N_DIM / 2)         // columns per half
#define N4      (N_DIM / 4)         // uint4 columns total
#define N4H     (NH / 4)            // uint4 columns per half

#define CT      128
#define LCH     (T_DIM / CT)        // 16 rows per chunk
#define BLOCK   256
#define MW      (N_DIM / 32)        // mask words per row

#define GAMMA_F 0.99f
#define GL_F    (0.99f * 0.95f)

// Scratch storage (no allocation allowed); accessed only via parameters.
__device__ uint32_t g_pack [T_DIM * N_DIM];   // (fp16(v)<<16) | fp16(delta)
__device__ uint32_t g_mask [T_DIM * MW];      // nonterminal bits
__device__ float2   g_AB   [CT * N_DIM];
__device__ float    g_carry[CT * N_DIM];

// ---------------------------------------------------------------------------
// Pass 1 (per half): read inputs once; emit compressed stream + aggregates.
// ---------------------------------------------------------------------------
__global__ __launch_bounds__(BLOCK, 8)
void gae_pass1(const float* __restrict__ rew,
               const float* __restrict__ val,
               const float* __restrict__ don,
               uint32_t* __restrict__ pack,
               uint32_t* __restrict__ mask,
               float2*   __restrict__ AB,
               int nOff)
{
    const int n  = nOff + blockIdx.x * BLOCK + threadIdx.x;
    const int k  = blockIdx.y;
    const int lo = k * LCH;
    const int hi = lo + LCH - 1;
    const int mw = n >> 5;
    const int lane0 = ((threadIdx.x & 31) == 0);

    float vn, dn;
    if (k == CT - 1) {
        vn = 0.0f; dn = 1.0f;
    } else {
        vn = val[(size_t)(hi + 1) * N_DIM + n];
        dn = don[(size_t)(hi + 1) * N_DIM + n];
    }

    float A = 0.0f, B = 1.0f;

    #pragma unroll
    for (int t = hi; t >= lo; --t) {
        const size_t idx = (size_t)t * N_DIM + n;
        const float rt = rew[idx];
        const float vt = val[idx];
        const float dt = don[idx];

        const float nt    = 1.0f - dn;
        const float delta = fmaf(GAMMA_F * nt, vn, rt) - vt;
        const float c     = GL_F * nt;

        const unsigned bal = __ballot_sync(0xffffffffu, dn < 0.5f);
        if (lane0) mask[(size_t)t * MW + mw] = bal;

        const uint32_t plo = (uint32_t)__half_as_ushort(__float2half_rn(delta));
        const uint32_t phi = (uint32_t)__half_as_ushort(__float2half_rn(vt));
        pack[idx] = (phi << 16) | plo;

        A = fmaf(c, A, delta);
        B = c * B;
        vn = vt;
        dn = dt;
    }

    AB[(size_t)k * N_DIM + n] = make_float2(A, B);
}

// ---------------------------------------------------------------------------
// Mid (per half): reverse fold over CT chunk aggregates -> carry per chunk.
// ---------------------------------------------------------------------------
__global__ __launch_bounds__(BLOCK)
void gae_mid(const float2* __restrict__ AB,
             float*        __restrict__ carry_out,
             int nOff)
{
    const int n = nOff + blockIdx.x * BLOCK + threadIdx.x;

    float carry = 0.0f;
    #pragma unroll 8
    for (int k = CT - 1; k >= 0; --k) {
        const size_t idx = (size_t)k * N_DIM + n;
        carry_out[idx] = carry;
        const float2 ab = AB[idx];
        carry = fmaf(ab.y, carry, ab.x);
    }
}

// ---------------------------------------------------------------------------
// Pass 2 (per half): recurrence from compressed stream; 4 columns/thread,
// STG.128 output stores. carry_in[k] indexes directly (CT2 == CT1).
// ---------------------------------------------------------------------------
__global__ __launch_bounds__(BLOCK, 4)
void gae_pass2(const uint4*    __restrict__ pack4,
               const uint32_t* __restrict__ mask,
               const float4*   __restrict__ carry_in,
               float4*         __restrict__ out,
               int c4Off)
{
    const int c4 = c4Off + blockIdx.x * BLOCK + threadIdx.x;   // uint4 column
    const int k  = blockIdx.y;
    const int lo = k * LCH;
    const int hi = lo + LCH - 1;

    const int n0   = 4 * c4;
    const int mw   = n0 >> 5;
    const int bit0 = n0 & 31;

    const float4 cr = carry_in[(size_t)k * N4 + c4];
    float a0 = cr.x, a1 = cr.y, a2 = cr.z, a3 = cr.w;

    float4* __restrict__ out_adv = out;
    float4* __restrict__ out_ret = out + (size_t)T_DIM * N4;

    #pragma unroll
    for (int t = hi; t >= lo; --t) {
        const size_t idx = (size_t)t * N4 + c4;
        const uint4    pk = pack4[idx];
        const uint32_t m  = mask[(size_t)t * MW + mw];

        const float d0 = __half2float(__ushort_as_half((unsigned short)(pk.x & 0xFFFFu)));
        const float v0 = __half2float(__ushort_as_half((unsigned short)(pk.x >> 16)));
        const float d1 = __half2float(__ushort_as_half((unsigned short)(pk.y & 0xFFFFu)));
        const float v1 = __half2float(__ushort_as_half((unsigned short)(pk.y >> 16)));
        const float d2 = __half2float(__ushort_as_half((unsigned short)(pk.z & 0xFFFFu)));
        const float v2 = __half2float(__ushort_as_half((unsigned short)(pk.z >> 16)));
        const float d3 = __half2float(__ushort_as_half((unsigned short)(pk.w & 0xFFFFu)));
        const float v3 = __half2float(__ushort_as_half((unsigned short)(pk.w >> 16)));

        const float c0 = ((m >> (bit0 + 0)) & 1u) ? GL_F : 0.0f;
        const float c1 = ((m >> (bit0 + 1)) & 1u) ? GL_F : 0.0f;
        const float c2 = ((m >> (bit0 + 2)) & 1u) ? GL_F : 0.0f;
        const float c3 = ((m >> (bit0 + 3)) & 1u) ? GL_F : 0.0f;

        a0 = fmaf(c0, a0, d0);
        a1 = fmaf(c1, a1, d1);
        a2 = fmaf(c2, a2, d2);
        a3 = fmaf(c3, a3, d3);

        out_adv[idx] = make_float4(a0, a1, a2, a3);
        out_ret[idx] = make_float4(a0 + v0, a1 + v1, a2 + v2, a3 + v3);
    }
}

// ---------------------------------------------------------------------------
extern "C" void kernel_launch(void* const* d_in, const int* in_sizes, int n_in,
                              void* d_out, int out_size)
{
    const float* rew = (const float*)d_in[0];
    const float* val = (const float*)d_in[1];
    const float* don = (const float*)d_in[2];

    void *p_pack, *p_mask, *p_AB, *p_carry;
    cudaGetSymbolAddress(&p_pack,  g_pack);
    cudaGetSymbolAddress(&p_mask,  g_mask);
    cudaGetSymbolAddress(&p_AB,    g_AB);
    cudaGetSymbolAddress(&p_carry, g_carry);

    uint32_t* pack = (uint32_t*)p_pack;
    uint32_t* mask = (uint32_t*)p_mask;
    float2*   AB   = (float2*)p_AB;
    float*    cry  = (float*)p_carry;

    // One-time resource init (idempotent; identical work every call).
    static cudaStream_t s2 = nullptr;
    static cudaEvent_t  evFork = nullptr, evJoin = nullptr;
    if (s2 == nullptr) {
        cudaStreamCreateWithFlags(&s2, cudaStreamNonBlocking);
        cudaEventCreateWithFlags(&evFork, cudaEventDisableTiming);
        cudaEventCreateWithFlags(&evJoin, cudaEventDisableTiming);
    }

    const dim3 blk(BLOCK);
    const dim3 grid1(NH / BLOCK, CT);      // 8 x 128 per half
    const dim3 gridM(NH / BLOCK);          // 8 blocks per half
    const dim3 grid2(N4H / BLOCK, CT);     // 2 x 128 per half

    // ---- half 0 pass1 on the main (capture) stream ----
    gae_pass1<<<grid1, blk, 0, 0>>>(rew, val, don, pack, mask, AB, 0);

    // fork: half 1's chain starts only after pass1(h0) -> skewed pipeline
    cudaEventRecord(evFork, 0);
    cudaStreamWaitEvent(s2, evFork, 0);

    // ---- main stream finishes half 0 (write-heavy pass2 overlaps s2's p1) --
    gae_mid  <<<gridM, blk, 0, 0>>>(AB, cry, 0);
    gae_pass2<<<grid2, blk, 0, 0>>>((const uint4*)pack, mask,
                                    (const float4*)cry, (float4*)d_out, 0);

    // ---- stream s2 runs half 1's full chain ----
    gae_pass1<<<grid1, blk, 0, s2>>>(rew, val, don, pack, mask, AB, NH);
    gae_mid  <<<gridM, blk, 0, s2>>>(AB, cry, NH);
    gae_pass2<<<grid2, blk, 0, s2>>>((const uint4*)pack, mask,
                                     (const float4*)cry, (float4*)d_out, NH / 4);

    // join
    cudaEventRecord(evJoin, s2);
    cudaStreamWaitEvent(0, evJoin, 0);
}

// round 17
// speedup vs baseline: 1.0748x; 1.0748x over previous
#include <cuda_runtime.h>
#include <cuda_fp16.h>
#include <cstdint>

// GAE reverse scan, 3-pass chunked linear recurrence with compressed
// intermediate (R15 base + PDL). R17: cache-policy pincer —
//   * pass1 input loads use __ldcs (read-ONCE in this scheme; evict-first so
//     they don't evict the freshly written pack/mask/AB intermediate), and
//   * pass2 output stores use __stcs (write-once; stay out of L2)
// so the 38.5 MB intermediate stays L2-resident between pass1 and pass2 and
// (in graph-replay steady state) never round-trips DRAM.
//
//   adv_t = delta_t + c_t * adv_{t+1},  c_t = GL*(1-done_{t+1})
//   delta_t = r_t + GAMMA*v_{t+1}*(1-done_{t+1}) - v_t   (v_T=0, done_T=1)
// Output: d_out[0:T*N] = advantages, d_out[T*N:2*T*N] = advantages + values.

#define T_DIM   2048
#define N_DIM   4096
#define N4      (N_DIM / 4)

#define CT      128
#define LCH     (T_DIM / CT)        // 16 rows per chunk
#define BLOCK   256
#define MW      (N_DIM / 32)        // mask words per row

#define GAMMA_F 0.99f
#define GL_F    (0.99f * 0.95f)

// Scratch storage (no allocation allowed); accessed only via parameters.
__device__ uint32_t g_pack [T_DIM * N_DIM];   // (fp16(v)<<16) | fp16(delta)
__device__ uint32_t g_mask [T_DIM * MW];      // nonterminal bits
__device__ float2   g_AB   [CT * N_DIM];
__device__ float    g_carry[CT * N_DIM];

// ---------------------------------------------------------------------------
// Pass 1: read inputs once (streaming); emit compressed stream + aggregates.
// ---------------------------------------------------------------------------
__global__ __launch_bounds__(BLOCK, 8)
void gae_pass1(const float* __restrict__ rew,
               const float* __restrict__ val,
               const float* __restrict__ don,
               uint32_t* __restrict__ pack,
               uint32_t* __restrict__ mask,
               float2*   __restrict__ AB)
{
    const int n  = blockIdx.x * BLOCK + threadIdx.x;
    const int k  = blockIdx.y;
    const int lo = k * LCH;
    const int hi = lo + LCH - 1;
    const int mw = n >> 5;
    const int lane0 = ((threadIdx.x & 31) == 0);

    float vn, dn;
    if (k == CT - 1) {
        vn = 0.0f; dn = 1.0f;
    } else {
        vn = __ldcs(&val[(size_t)(hi + 1) * N_DIM + n]);
        dn = __ldcs(&don[(size_t)(hi + 1) * N_DIM + n]);
    }

    float A = 0.0f, B = 1.0f;

    #pragma unroll
    for (int t = hi; t >= lo; --t) {
        const size_t idx = (size_t)t * N_DIM + n;
        const float rt = __ldcs(&rew[idx]);
        const float vt = __ldcs(&val[idx]);
        const float dt = __ldcs(&don[idx]);

        const float nt    = 1.0f - dn;
        const float delta = fmaf(GAMMA_F * nt, vn, rt) - vt;
        const float c     = GL_F * nt;

        const unsigned bal = __ballot_sync(0xffffffffu, dn < 0.5f);
        if (lane0) mask[(size_t)t * MW + mw] = bal;

        const uint32_t plo = (uint32_t)__half_as_ushort(__float2half_rn(delta));
        const uint32_t phi = (uint32_t)__half_as_ushort(__float2half_rn(vt));
        pack[idx] = (phi << 16) | plo;

        A = fmaf(c, A, delta);
        B = c * B;
        vn = vt;
        dn = dt;
    }

    AB[(size_t)k * N_DIM + n] = make_float2(A, B);

    cudaTriggerProgrammaticLaunchCompletion();
}

// ---------------------------------------------------------------------------
// Mid: per-column reverse fold over CT chunk aggregates -> carry per chunk.
// ---------------------------------------------------------------------------
__global__ __launch_bounds__(BLOCK)
void gae_mid(const float2* __restrict__ AB,
             float*        __restrict__ carry_out)
{
    cudaGridDependencySynchronize();

    const int n = blockIdx.x * BLOCK + threadIdx.x;

    float carry = 0.0f;
    #pragma unroll 8
    for (int k = CT - 1; k >= 0; --k) {
        const size_t idx = (size_t)k * N_DIM + n;
        carry_out[idx] = carry;
        const float2 ab = AB[idx];
        carry = fmaf(ab.y, carry, ab.x);
    }

    cudaTriggerProgrammaticLaunchCompletion();
}

// ---------------------------------------------------------------------------
// Pass 2: recurrence from compressed stream (L2-resident); 4 columns/thread,
// streaming STG.128 output stores. carry_in[k] indexes directly.
// ---------------------------------------------------------------------------
__global__ __launch_bounds__(BLOCK, 4)
void gae_pass2(const uint4*    __restrict__ pack4,
               const uint32_t* __restrict__ mask,
               const float4*   __restrict__ carry_in,
               float4*         __restrict__ out)
{
    cudaGridDependencySynchronize();

    const int c4 = blockIdx.x * BLOCK + threadIdx.x;   // uint4 column
    const int k  = blockIdx.y;
    const int lo = k * LCH;
    const int hi = lo + LCH - 1;

    const int n0   = 4 * c4;
    const int mw   = n0 >> 5;
    const int bit0 = n0 & 31;

    const float4 cr = carry_in[(size_t)k * N4 + c4];
    float a0 = cr.x, a1 = cr.y, a2 = cr.z, a3 = cr.w;

    float4* __restrict__ out_adv = out;
    float4* __restrict__ out_ret = out + (size_t)T_DIM * N4;

    #pragma unroll
    for (int t = hi; t >= lo; --t) {
        const size_t idx = (size_t)t * N4 + c4;
        const uint4    pk = pack4[idx];
        const uint32_t m  = mask[(size_t)t * MW + mw];

        const float d0 = __half2float(__ushort_as_half((unsigned short)(pk.x & 0xFFFFu)));
        const float v0 = __half2float(__ushort_as_half((unsigned short)(pk.x >> 16)));
        const float d1 = __half2float(__ushort_as_half((unsigned short)(pk.y & 0xFFFFu)));
        const float v1 = __half2float(__ushort_as_half((unsigned short)(pk.y >> 16)));
        const float d2 = __half2float(__ushort_as_half((unsigned short)(pk.z & 0xFFFFu)));
        const float v2 = __half2float(__ushort_as_half((unsigned short)(pk.z >> 16)));
        const float d3 = __half2float(__ushort_as_half((unsigned short)(pk.w & 0xFFFFu)));
        const float v3 = __half2float(__ushort_as_half((unsigned short)(pk.w >> 16)));

        const float c0 = ((m >> (bit0 + 0)) & 1u) ? GL_F : 0.0f;
        const float c1 = ((m >> (bit0 + 1)) & 1u) ? GL_F : 0.0f;
        const float c2 = ((m >> (bit0 + 2)) & 1u) ? GL_F : 0.0f;
        const float c3 = ((m >> (bit0 + 3)) & 1u) ? GL_F : 0.0f;

        a0 = fmaf(c0, a0, d0);
        a1 = fmaf(c1, a1, d1);
        a2 = fmaf(c2, a2, d2);
        a3 = fmaf(c3, a3, d3);

        __stcs(&out_adv[idx], make_float4(a0, a1, a2, a3));
        __stcs(&out_ret[idx], make_float4(a0 + v0, a1 + v1, a2 + v2, a3 + v3));
    }
}

// ---------------------------------------------------------------------------
extern "C" void kernel_launch(void* const* d_in, const int* in_sizes, int n_in,
                              void* d_out, int out_size)
{
    const float* rew = (const float*)d_in[0];
    const float* val = (const float*)d_in[1];
    const float* don = (const float*)d_in[2];

    void *p_pack, *p_mask, *p_AB, *p_carry;
    cudaGetSymbolAddress(&p_pack,  g_pack);
    cudaGetSymbolAddress(&p_mask,  g_mask);
    cudaGetSymbolAddress(&p_AB,    g_AB);
    cudaGetSymbolAddress(&p_carry, g_carry);

    // pass1: normal launch
    {
        dim3 grid(N_DIM / BLOCK, CT);
        gae_pass1<<<grid, dim3(BLOCK)>>>(rew, val, don,
                                         (uint32_t*)p_pack, (uint32_t*)p_mask,
                                         (float2*)p_AB);
    }

    // mid: PDL-chained behind pass1
    {
        cudaLaunchConfig_t cfg = {};
        cfg.gridDim  = dim3(N_DIM / BLOCK);
        cfg.blockDim = dim3(BLOCK);
        cfg.stream   = 0;
        cudaLaunchAttribute attr[1];
        attr[0].id = cudaLaunchAttributeProgrammaticStreamSerialization;
        attr[0].val.programmaticStreamSerializationAllowed = 1;
        cfg.attrs = attr;
        cfg.numAttrs = 1;
        cudaLaunchKernelEx(&cfg, gae_mid,
                           (const float2*)p_AB, (float*)p_carry);
    }

    // pass2: PDL-chained behind mid
    {
        cudaLaunchConfig_t cfg = {};
        cfg.gridDim  = dim3(N4 / BLOCK, CT);   // 4 x 128 = 512 blocks
        cfg.blockDim = dim3(BLOCK);
        cfg.stream   = 0;
        cudaLaunchAttribute attr[1];
        attr[0].id = cudaLaunchAttributeProgrammaticStreamSerialization;
        attr[0].val.programmaticStreamSerializationAllowed = 1;
        cfg.attrs = attr;
        cfg.numAttrs = 1;
        cudaLaunchKernelEx(&cfg, gae_pass2,
                           (const uint4*)p_pack, (const uint32_t*)p_mask,
                           (const float4*)p_carry, (float4*)d_out);
    }
}